// round 6
// baseline (speedup 1.0000x reference)
#include <cuda_runtime.h>
#include <math.h>

// Problem constants (fixed by the dataset): B=256, K=512, D=1024
#define B_SZ 256
#define K_SZ 512
#define D_SZ 1024
#define INV_T (1.0f / 0.07f)

// grid = 2048: 8 blocks per sample, 8 warps per block, 8 k-rows per warp
#define BLOCKS_PER_B 8
#define K_PER_WARP 8
#define NBLK (B_SZ * BLOCKS_PER_B)   // 2048

// Scratch (no cudaMalloc allowed)
__device__ float g_fg_per_b[B_SZ];     // exp(fg_logit / T) per sample
__device__ float g_part[NBLK];         // per-block partial sums (8 KB)
__device__ unsigned int g_count;       // arrival counter (zero-init, self-resetting)

// ---------------------------------------------------------------------------
// Single fused kernel. Streaming loop is pure LDG+FMA (per-lane accumulators,
// one per k-row); ALL warp reductions/exps deferred to after the loop so the
// load pipe never drains. Last-arriving block reduces 2048 partials.
// grid = 2048, block = 256
// ---------------------------------------------------------------------------
__global__ void __launch_bounds__(256) fused_kernel(
    const float* __restrict__ img,
    const float* __restrict__ fg,
    const float* __restrict__ pro,
    float* __restrict__ out)
{
    __shared__ float4 s_img[256];   // 4 KB: the img row
    __shared__ float  s_ss[8];
    __shared__ float  s_fg[8];
    __shared__ float  s_part[8];
    __shared__ int    s_last;

    const int blk  = blockIdx.x;
    const int b    = blk >> 3;          // blk / BLOCKS_PER_B
    const int kgrp = blk & 7;           // blk % BLOCKS_PER_B
    const int t    = threadIdx.x;
    const int w    = t >> 5;
    const int l    = t & 31;

    // ---- load img row into smem + sum of squares ----
    float4 v = ((const float4*)(img + (size_t)b * D_SZ))[t];
    s_img[t] = v;

    float ss = v.x * v.x + v.y * v.y + v.z * v.z + v.w * v.w;
    #pragma unroll
    for (int o = 16; o > 0; o >>= 1)
        ss += __shfl_xor_sync(0xFFFFFFFFu, ss, o);
    if (l == 0) s_ss[w] = ss;
    __syncthreads();

    float tss = 0.f;
    #pragma unroll
    for (int i = 0; i < 8; i++) tss += s_ss[i];
    const float inv = 1.0f / sqrtf(tss);

    // ---- fg dot: only in the first block of each sample ----
    if (kgrp == 0) {
        float4 f = ((const float4*)(fg + (size_t)b * D_SZ))[t];
        float fd = v.x * f.x + v.y * f.y + v.z * f.z + v.w * f.w;
        #pragma unroll
        for (int o = 16; o > 0; o >>= 1)
            fd += __shfl_xor_sync(0xFFFFFFFFu, fd, o);
        if (l == 0) s_fg[w] = fd;
        __syncthreads();
        if (t == 0) {
            float tfd = 0.f;
            #pragma unroll
            for (int i = 0; i < 8; i++) tfd += s_fg[i];
            g_fg_per_b[b] = expf(tfd * inv * INV_T);
        }
    }

    // ---- each warp: 8 consecutive (b,k) rows streamed from DRAM ----
    // Pure load+FMA loop: per-lane partial dot per row; reductions deferred.
    const int kbase = (kgrp << 6) + (w << 3);   // kgrp*64 + w*8
    const float4* p4 = (const float4*)(pro + ((size_t)b * K_SZ + kbase) * D_SZ);

    float accr[K_PER_WARP];
    #pragma unroll
    for (int r = 0; r < K_PER_WARP; r++) accr[r] = 0.f;

    #pragma unroll
    for (int r = 0; r < K_PER_WARP; r++) {
        const float4* row = p4 + (size_t)r * 256;   // 1024 floats = 256 float4

        float4 p[8];
        #pragma unroll
        for (int j = 0; j < 8; j++)
            p[j] = __ldcs(row + j * 32 + l);        // 8 independent LDG.128

        float a = 0.f;
        #pragma unroll
        for (int j = 0; j < 8; j++) {
            float4 q = s_img[j * 32 + l];
            a += q.x * p[j].x + q.y * p[j].y + q.z * p[j].z + q.w * p[j].w;
        }
        accr[r] = a;
    }

    // ---- deferred reductions: 8 warp-reduces + exps, once per warp ----
    float wsum = 0.f;
    #pragma unroll
    for (int r = 0; r < K_PER_WARP; r++) {
        float a = accr[r];
        #pragma unroll
        for (int o = 16; o > 0; o >>= 1)
            a += __shfl_xor_sync(0xFFFFFFFFu, a, o);
        if (l == 0) wsum += expf(a * inv * INV_T);
    }

    if (l == 0) s_part[w] = wsum;
    __syncthreads();

    // ---- publish partial, arrive at counter; detect last block ----
    if (t == 0) {
        float tsum = 0.f;
        #pragma unroll
        for (int i = 0; i < 8; i++) tsum += s_part[i];
        g_part[blk] = tsum;
        __threadfence();                          // make partial + fg visible
        unsigned r = atomicAdd(&g_count, 1u);
        s_last = (r == (unsigned)(NBLK - 1));
    }
    __syncthreads();
    if (!s_last) return;

    // =======================================================================
    // Final deterministic reduce — one block, 2048 partials (L2-hot),
    // 512 LDG.128 total. Fixed read order -> replay-deterministic.
    // =======================================================================
    if (t == 0) g_count = 0;                      // reset for next graph replay

    const float4* gp4 = (const float4*)g_part;    // 512 float4
    float4 x0 = gp4[t];
    float4 x1 = gp4[t + 256];
    float  fgv = g_fg_per_b[t];                   // t in [0,256)

    double acc2 = ((double)x0.x + (double)x0.y) + ((double)x0.z + (double)x0.w)
                + ((double)x1.x + (double)x1.y) + ((double)x1.z + (double)x1.w);
    double fgd  = (double)fgv;

    #pragma unroll
    for (int o = 16; o > 0; o >>= 1) {
        acc2 += __shfl_xor_sync(0xFFFFFFFFu, acc2, o);
        fgd  += __shfl_xor_sync(0xFFFFFFFFu, fgd,  o);
    }

    __shared__ double sa[8];
    __shared__ double sfd[8];
    if (l == 0) { sa[w] = acc2; sfd[w] = fgd; }
    __syncthreads();

    if (t == 0) {
        double a = 0.0, f = 0.0;
        #pragma unroll
        for (int i = 0; i < 8; i++) { a += sa[i]; f += sfd[i]; }
        double pos = a / (double)K_SZ;            // sum_b mean_k exp(...)
        double neg = pos + f;
        out[0] = (float)(-log(pos / neg));
    }
}

// ---------------------------------------------------------------------------
extern "C" void kernel_launch(void* const* d_in, const int* in_sizes, int n_in,
                              void* d_out, int out_size)
{
    const float* img = (const float*)d_in[0];  // bg_img_feature [256,1024]
    const float* fg  = (const float*)d_in[1];  // fg_pro_feature [256,1024]
    const float* pro = (const float*)d_in[2];  // bg_pro_feature [256,512,1024]

    fused_kernel<<<NBLK, 256>>>(img, fg, pro, (float*)d_out);
}

// round 7
// speedup vs baseline: 1.0277x; 1.0277x over previous
#include <cuda_runtime.h>
#include <math.h>

// Problem constants (fixed by the dataset): B=256, K=512, D=1024
#define B_SZ 256
#define K_SZ 512
#define D_SZ 1024
#define INV_T (1.0f / 0.07f)

#define K_PER_BLOCK 8                      // 8 warps per block, one k per warp
#define BLOCKS_PER_B (K_SZ / K_PER_BLOCK)  // 64
#define NBLK (B_SZ * BLOCKS_PER_B)         // 16384

#define RBLK 64                            // reduce kernel blocks

// Scratch (no cudaMalloc allowed)
__device__ float g_fg_per_b[B_SZ];       // exp(fg_logit / T) per sample
__device__ float g_part[NBLK];           // per-block partial sums
__device__ float g_p2[RBLK];             // stage-2 partials
__device__ float g_f2[RBLK];             // stage-2 fg partials
__device__ unsigned int g_count2;        // stage-2 arrival counter (zero-init)

// ---------------------------------------------------------------------------
// Kernel A (the proven 7.2 TB/s streamer, R2 structure): per-block img-row
// normalization + 8 warps each streaming ONE pro row; block exits fast.
// grid = 16384, block = 256
// ---------------------------------------------------------------------------
__global__ void __launch_bounds__(256) fused_kernel(
    const float* __restrict__ img,
    const float* __restrict__ fg,
    const float* __restrict__ pro)
{
    __shared__ float4 s_img[256];   // 4 KB: the img row
    __shared__ float  s_ss[8];
    __shared__ float  s_fg[8];
    __shared__ float  s_part[8];

    const int blk  = blockIdx.x;
    const int b    = blk >> 6;          // blk / BLOCKS_PER_B
    const int kgrp = blk & 63;          // blk % BLOCKS_PER_B
    const int t    = threadIdx.x;
    const int w    = t >> 5;
    const int l    = t & 31;

    // ---- load img row into smem + sum of squares ----
    float4 v = ((const float4*)(img + (size_t)b * D_SZ))[t];
    s_img[t] = v;

    float ss = v.x * v.x + v.y * v.y + v.z * v.z + v.w * v.w;
    #pragma unroll
    for (int o = 16; o > 0; o >>= 1)
        ss += __shfl_xor_sync(0xFFFFFFFFu, ss, o);
    if (l == 0) s_ss[w] = ss;
    __syncthreads();

    float tss = 0.f;
    #pragma unroll
    for (int i = 0; i < 8; i++) tss += s_ss[i];
    const float inv = 1.0f / sqrtf(tss);

    // ---- fg dot: only in the first block of each sample ----
    if (kgrp == 0) {
        float4 f = ((const float4*)(fg + (size_t)b * D_SZ))[t];
        float fd = v.x * f.x + v.y * f.y + v.z * f.z + v.w * f.w;
        #pragma unroll
        for (int o = 16; o > 0; o >>= 1)
            fd += __shfl_xor_sync(0xFFFFFFFFu, fd, o);
        if (l == 0) s_fg[w] = fd;
        __syncthreads();
        if (t == 0) {
            float tfd = 0.f;
            #pragma unroll
            for (int i = 0; i < 8; i++) tfd += s_fg[i];
            g_fg_per_b[b] = expf(tfd * inv * INV_T);
        }
    }

    // ---- each warp: one (b,k) dot, pro streamed from DRAM ----
    const int k = (kgrp << 3) + w;
    const float4* p4 = (const float4*)(pro + ((size_t)b * K_SZ + k) * D_SZ);

    float4 p[8];
    #pragma unroll
    for (int j = 0; j < 8; j++)
        p[j] = p4[j * 32 + l];              // 8 independent LDG.128

    float acc = 0.f;
    #pragma unroll
    for (int j = 0; j < 8; j++) {
        float4 a = s_img[j * 32 + l];
        acc += a.x * p[j].x + a.y * p[j].y + a.z * p[j].z + a.w * p[j].w;
    }

    #pragma unroll
    for (int o = 16; o > 0; o >>= 1)
        acc += __shfl_xor_sync(0xFFFFFFFFu, acc, o);
    if (l == 0) s_part[w] = expf(acc * inv * INV_T);
    __syncthreads();

    if (t == 0) {
        float tsum = 0.f;
        #pragma unroll
        for (int i = 0; i < 8; i++) tsum += s_part[i];
        g_part[blk] = tsum;   // fixed order: deterministic across replays
    }
}

// ---------------------------------------------------------------------------
// Kernel B: grid-64 tree reduce. Block j folds g_part[j*256 .. j*256+255]
// and g_fg_per_b[j*4 .. j*4+3]; last arriving block folds the 64 stage-2
// values and writes the loss. All orders fixed -> replay-deterministic.
// grid = 64, block = 256
// ---------------------------------------------------------------------------
__global__ void __launch_bounds__(256) reduce_kernel(float* __restrict__ out)
{
    __shared__ double sa[8];
    __shared__ double sf[8];
    __shared__ int    s_last;

    const int j = blockIdx.x;
    const int t = threadIdx.x;
    const int w = t >> 5;
    const int l = t & 31;

    // ---- stage 1: 256 partials + 4 fg terms per block ----
    double a = (double)g_part[j * 256 + t];
    double f = (t < 4) ? (double)g_fg_per_b[j * 4 + t] : 0.0;

    #pragma unroll
    for (int o = 16; o > 0; o >>= 1) {
        a += __shfl_xor_sync(0xFFFFFFFFu, a, o);
        f += __shfl_xor_sync(0xFFFFFFFFu, f, o);
    }
    if (l == 0) { sa[w] = a; sf[w] = f; }
    __syncthreads();

    if (t == 0) {
        double ta = 0.0, tf = 0.0;
        #pragma unroll
        for (int i = 0; i < 8; i++) { ta += sa[i]; tf += sf[i]; }
        g_p2[j] = (float)ta;
        g_f2[j] = (float)tf;
        __threadfence();
        unsigned r = atomicAdd(&g_count2, 1u);
        s_last = (r == (unsigned)(RBLK - 1));
    }
    __syncthreads();
    if (!s_last) return;

    // ---- stage 2: last block folds 64 + 64 values ----
    if (t == 0) g_count2 = 0;                 // reset for next graph replay

    if (w < 2) {                              // 64 threads
        double a2 = (double)g_p2[t];
        double f2 = (double)g_f2[t];
        #pragma unroll
        for (int o = 16; o > 0; o >>= 1) {
            a2 += __shfl_xor_sync(0xFFFFFFFFu, a2, o);
            f2 += __shfl_xor_sync(0xFFFFFFFFu, f2, o);
        }
        if (l == 0) { sa[w] = a2; sf[w] = f2; }
    }
    __syncthreads();

    if (t == 0) {
        double pos = (sa[0] + sa[1]) / (double)K_SZ;  // sum_b mean_k exp(...)
        double neg = pos + (sf[0] + sf[1]);
        out[0] = (float)(-log(pos / neg));
    }
}

// ---------------------------------------------------------------------------
extern "C" void kernel_launch(void* const* d_in, const int* in_sizes, int n_in,
                              void* d_out, int out_size)
{
    const float* img = (const float*)d_in[0];  // bg_img_feature [256,1024]
    const float* fg  = (const float*)d_in[1];  // fg_pro_feature [256,1024]
    const float* pro = (const float*)d_in[2];  // bg_pro_feature [256,512,1024]

    fused_kernel<<<NBLK, 256>>>(img, fg, pro);
    reduce_kernel<<<RBLK, 256>>>((float*)d_out);
}